// round 1
// baseline (speedup 1.0000x reference)
#include <cuda_runtime.h>

// ---------------- problem-size capacities (fixed by dataset) ----------------
static const int NMAX  = 100000;   // nodes
static const int EMAX  = 500000;   // edges per layer
static const int QMAXC = 128;      // queries

// ---------------- device scratch (static; no allocation) --------------------
__device__ float    dM[128 * 128];          // M = Wq^T @ Wk
__device__ float    dGx[QMAXC * 32];        // per-query: dot with x = repr[src]
__device__ float    dGy[QMAXC * 32];        // per-query: dot with y = repr[dst]
__device__ float    dGrel[QMAXC * 32];      // per-query: dot with rel
__device__ float    dCq[QMAXC];             // per-query scalar
__device__ float    dZ[NMAX * 32];          // M00 @ repr   (dst side)
__device__ float    dP[NMAX * 32];          // M01^T @ repr (src side, dot rel)
__device__ float    dT[NMAX * 32];          // M10 @ repr   (dst side, dot rel)
__device__ float    dRepr[NMAX * 32];       // repr_ after layer-1 update
__device__ float    dAgg[NMAX * 32];        // segment-sum accumulator
__device__ float    dLogits[EMAX];
__device__ float    dEx[EMAX];
__device__ unsigned dTsEnc[EMAX];           // target_score as orderable bits
__device__ unsigned dNodeMax[NMAX];         // encoded per-src max logit
__device__ float    dNodeSum[NMAX];         // per-src softmax denominator
__device__ int      dOff[QMAXC + 1];        // eg-group offsets
__device__ int      dKlist[EMAX];           // kept-edge compacted list
__device__ int      dKcount;

// ---------------- helpers ----------------------------------------------------
__device__ __forceinline__ unsigned encf(float f) {
    unsigned u = __float_as_uint(f);
    return (u & 0x80000000u) ? ~u : (u | 0x80000000u);
}
__device__ __forceinline__ float decf(unsigned e) {
    unsigned u = (e & 0x80000000u) ? (e & 0x7FFFFFFFu) : ~e;
    return __uint_as_float(u);
}

// ---------------- kernels -----------------------------------------------------

// M[i][j] = sum_o Wq[o][i] * Wk[o][j]
__global__ void computeM_k(const float* __restrict__ Wq, const float* __restrict__ Wk) {
    int i = blockIdx.x, j = threadIdx.x;
    float acc = 0.f;
    #pragma unroll 8
    for (int o = 0; o < 128; o++)
        acc = fmaf(Wq[o * 128 + i], Wk[o * 128 + j], acc);
    dM[i * 128 + j] = acc;
}

// Per-query precompute. One block (32 threads) per query.
__global__ void query_pre_k(const float* __restrict__ qemb, const float* __restrict__ remb) {
    int q = blockIdx.x, d = threadIdx.x;
    __shared__ float qv[32], rv[32];
    qv[d] = qemb[q * 32 + d];
    rv[d] = remb[q * 32 + d];
    __syncwarp();
    float gx = 0.f, gy = 0.f, gr = 0.f;
    for (int k = 0; k < 32; k++) {
        float qk = qv[k], rk = rv[k];
        gx = fmaf(dM[d * 128 + 64 + k], qk, gx);
        gx = fmaf(dM[d * 128 + 96 + k], rk, gx);
        gy = fmaf(dM[(64 + k) * 128 + d], qk, gy);
        gy = fmaf(dM[(96 + k) * 128 + d], rk, gy);
        gr = fmaf(dM[(32 + d) * 128 + 64 + k], qk, gr);
        gr = fmaf(dM[(32 + d) * 128 + 96 + k], rk, gr);
        gr = fmaf(dM[(64 + k) * 128 + 32 + d], qk, gr);
        gr = fmaf(dM[(96 + k) * 128 + 32 + d], rk, gr);
    }
    dGx[q * 32 + d] = gx;
    dGy[q * 32 + d] = gy;
    dGrel[q * 32 + d] = gr;
    float c = 0.f;
    for (int l = 0; l < 32; l++) {
        c = fmaf(qv[d], fmaf(dM[(64 + d) * 128 + 64 + l], qv[l], dM[(64 + d) * 128 + 96 + l] * rv[l]), c);
        c = fmaf(rv[d], fmaf(dM[(96 + d) * 128 + 64 + l], qv[l], dM[(96 + d) * 128 + 96 + l] * rv[l]), c);
    }
    for (int off = 16; off; off >>= 1) c += __shfl_xor_sync(0xffffffffu, c, off);
    if (d == 0) dCq[q] = c;
}

// Reset accumulators. If score_out != null also zero the output score region.
__global__ void reset_k(float* score_out, int N) {
    int i = blockIdx.x * blockDim.x + threadIdx.x;
    if (i < N * 32) dAgg[i] = 0.f;
    if (i < N) {
        dNodeMax[i] = 0u;
        dNodeSum[i] = 0.f;
        if (score_out) score_out[i] = 0.f;
    }
    if (i == 0) dKcount = 0;
}

// Per-node: z = M00 r, p = M01^T r, t = M10 r. One warp per node.
__global__ void node_pre_k(const float* repr_ext, int use_internal, int N) {
    __shared__ float sZ[1024], sP[1024], sT[1024];
    int tid = threadIdx.x;
    for (int i = tid; i < 1024; i += blockDim.x) {
        int j = i & 31, k = i >> 5;                // storage: [k][j]
        sZ[i] = dM[j * 128 + k];                   // M00[j][k]
        sP[i] = dM[k * 128 + 32 + j];              // M01[k][j]
        sT[i] = dM[(32 + j) * 128 + k];            // M10[j][k]
    }
    __syncthreads();
    const float* repr = use_internal ? dRepr : repr_ext;
    int node = blockIdx.x * 8 + (tid >> 5);
    int j = tid & 31;
    if (node >= N) return;
    float r = repr[node * 32 + j];
    float z = 0.f, p = 0.f, t = 0.f;
    #pragma unroll
    for (int k = 0; k < 32; k++) {
        float rk = __shfl_sync(0xffffffffu, r, k);
        z = fmaf(sZ[k * 32 + j], rk, z);
        p = fmaf(sP[k * 32 + j], rk, p);
        t = fmaf(sT[k * 32 + j], rk, t);
    }
    dZ[node * 32 + j] = z;
    dP[node * 32 + j] = p;
    dT[node * 32 + j] = t;
}

// Edge logits. One warp per edge.
__global__ void edge_logits_k(const int* __restrict__ src, const int* __restrict__ dst,
                              const int* __restrict__ eg, const float* __restrict__ rel,
                              const float* repr_ext, int use_internal, int E) {
    __shared__ float sM11T[1024];                  // [k][j] = M11[j][k]
    int tid = threadIdx.x;
    for (int i = tid; i < 1024; i += blockDim.x) {
        int j = i & 31, k = i >> 5;
        sM11T[i] = dM[(32 + j) * 128 + (32 + k)];
    }
    __syncthreads();
    const float* repr = use_internal ? dRepr : repr_ext;
    int e = (int)((blockIdx.x * (unsigned)blockDim.x + tid) >> 5);
    int j = tid & 31;
    if (e >= E) return;
    int s = __ldg(&src[e]), d = __ldg(&dst[e]), g = __ldg(&eg[e]);
    float x  = repr[s * 32 + j];
    float y  = repr[d * 32 + j];
    float zz = dZ[d * 32 + j];
    float pp = dP[s * 32 + j];
    float tt = dT[d * 32 + j];
    float re = rel[(size_t)e * 32 + j];
    float gxv = dGx[g * 32 + j], gyv = dGy[g * 32 + j], grv = dGrel[g * 32 + j];
    float w = 0.f;
    #pragma unroll
    for (int k = 0; k < 32; k++) {
        float rk = __shfl_sync(0xffffffffu, re, k);
        w = fmaf(sM11T[k * 32 + j], rk, w);
    }
    float part = x * (zz + gxv) + y * gyv + re * (pp + tt + grv + w);
    #pragma unroll
    for (int off = 16; off; off >>= 1) part += __shfl_xor_sync(0xffffffffu, part, off);
    if (j == 0) {
        float logit = part + dCq[g];
        dLogits[e] = logit;
        atomicMax(&dNodeMax[s], encf(logit));
    }
}

// exp(logit - max) + per-src sum. Thread per edge.
__global__ void edge_exp_k(const int* __restrict__ src, int E) {
    int e = blockIdx.x * blockDim.x + threadIdx.x;
    if (e >= E) return;
    int s = src[e];
    float m = decf(dNodeMax[s]);
    float ex = expf(dLogits[e] - m);
    dEx[e] = ex;
    atomicAdd(&dNodeSum[s], ex);
}

// target_score = (ex/sum) * visited_score[src], encoded (nonnegative -> raw bits).
__global__ void ts_k(const int* __restrict__ src, const float* __restrict__ vscore, int E) {
    int e = blockIdx.x * blockDim.x + threadIdx.x;
    if (e >= E) return;
    int s = src[e];
    float w = dEx[e] / dNodeSum[s];
    dTsEnc[e] = __float_as_uint(w * vscore[s]);
}

// eg-group offsets by binary search (eg sorted, values in [0,Q)).
__global__ void group_off_k(const int* __restrict__ eg, int E, int Q) {
    int g = blockIdx.x * blockDim.x + threadIdx.x;
    if (g > Q) return;
    int lo = 0, hi = E;
    while (lo < hi) {
        int mid = (lo + hi) >> 1;
        if (eg[mid] < g) lo = mid + 1; else hi = mid;
    }
    dOff[g] = lo;
}

// Per-group top-k with exact stable tie-break (value desc, index asc).
// One block per eg group: 8-bit radix select then in-order chunked keep scan.
__global__ void topk_k(const int* maxe) {
    int g = blockIdx.x;
    int lo = dOff[g], hi = dOff[g + 1];
    int len = hi - lo;
    if (len <= 0) return;
    int K = maxe ? maxe[0] : 500;
    if (K > len) K = len;

    __shared__ int hist[256];
    __shared__ int s_selbin, s_rem;
    unsigned prefix = 0u;
    int remaining = K;
    for (int shift = 24; shift >= 0; shift -= 8) {
        unsigned mask_hi = (shift == 24) ? 0u : (0xFFFFFFFFu << (shift + 8));
        for (int i = threadIdx.x; i < 256; i += blockDim.x) hist[i] = 0;
        __syncthreads();
        for (int i = lo + threadIdx.x; i < hi; i += blockDim.x) {
            unsigned v = dTsEnc[i];
            if ((v & mask_hi) == prefix) atomicAdd(&hist[(v >> shift) & 255], 1);
        }
        __syncthreads();
        if (threadIdx.x == 0) {
            int cum = 0, b = 255;
            for (; b > 0; b--) { cum += hist[b]; if (cum >= remaining) break; }
            if (cum < remaining) cum += hist[0];      // b == 0 fallthrough
            s_selbin = b;
            s_rem = remaining - (cum - hist[b]);      // minus strictly-greater bins
        }
        __syncthreads();
        prefix |= ((unsigned)s_selbin) << shift;
        remaining = s_rem;
        __syncthreads();
    }
    unsigned T = prefix;
    int quota_eq = remaining;

    __shared__ int warp_cnt[8];
    __shared__ int s_running;
    if (threadIdx.x == 0) s_running = 0;
    __syncthreads();
    for (int base = lo; base < hi; base += blockDim.x) {
        int i = base + (int)threadIdx.x;
        bool valid = i < hi;
        unsigned v = valid ? dTsEnc[i] : 0u;
        bool gt = valid && (v > T);
        bool eq = valid && (v == T);
        unsigned bal = __ballot_sync(0xffffffffu, eq);
        int lane = threadIdx.x & 31, wrp = threadIdx.x >> 5;
        int myrank = __popc(bal & ((1u << lane) - 1u));
        if (lane == 0) warp_cnt[wrp] = __popc(bal);
        __syncthreads();
        int woff = 0, chunk_tot = 0;
        #pragma unroll
        for (int ww = 0; ww < 8; ww++) {
            int c = warp_cnt[ww];
            if (ww < wrp) woff += c;
            chunk_tot += c;
        }
        int rank = s_running + woff + myrank;
        bool keep = gt || (eq && rank < quota_eq);
        if (keep) {
            int pos = atomicAdd(&dKcount, 1);
            dKlist[pos] = i;
        }
        __syncthreads();
        if (threadIdx.x == 0) s_running += chunk_tot;
        __syncthreads();
    }
}

// Layer-1 scatter over kept edges only. One warp per kept edge.
__global__ void scatter1_k(const int* __restrict__ src, const int* __restrict__ dst,
                           const float* __restrict__ node_repr, const float* __restrict__ vscore,
                           float* __restrict__ score_out) {
    int i = (int)((blockIdx.x * (unsigned)blockDim.x + threadIdx.x) >> 5);
    int j = threadIdx.x & 31;
    if (i >= dKcount) return;
    int e = dKlist[i];
    int s = src[e], d = dst[e];
    float w = dEx[e] / dNodeSum[s];
    atomicAdd(&dAgg[d * 32 + j], w * node_repr[s * 32 + j]);
    if (j == 0) atomicAdd(&score_out[d], w * vscore[s]);
}

// repr_ = 0.8*agg + 0.2*node_repr
__global__ void repr_upd_k(const float* __restrict__ node_repr, int N) {
    int i = blockIdx.x * blockDim.x + threadIdx.x;
    if (i < N * 32) dRepr[i] = fmaf(0.8f, dAgg[i], 0.2f * node_repr[i]);
}

// Layer-0 scatter over ALL edges. One warp per edge.
__global__ void scatter0_k(const int* __restrict__ src, const int* __restrict__ dst, int E) {
    int e = (int)((blockIdx.x * (unsigned)blockDim.x + threadIdx.x) >> 5);
    int j = threadIdx.x & 31;
    if (e >= E) return;
    int s = src[e], d = dst[e];
    float w = dEx[e] / dNodeSum[s];
    atomicAdd(&dAgg[d * 32 + j], w * dRepr[s * 32 + j]);
}

// Final: r2 = 0.8*agg0 + 0.2*repr_; out = LeakyReLU(Wlin @ r2 + blin). Warp/node.
__global__ void final_k(const float* __restrict__ Wlin, const float* __restrict__ blin,
                        float* __restrict__ out_repr, int N) {
    __shared__ float sW[1024];                     // [j][l] = Wlin[l][j]
    int tid = threadIdx.x;
    for (int i = tid; i < 1024; i += blockDim.x) {
        int l = i & 31, j = i >> 5;
        sW[i] = Wlin[l * 32 + j];
    }
    __syncthreads();
    int node = blockIdx.x * 8 + (tid >> 5);
    int l = tid & 31;
    if (node >= N) return;
    float r2 = fmaf(0.8f, dAgg[node * 32 + l], 0.2f * dRepr[node * 32 + l]);
    float h = blin[l];
    #pragma unroll
    for (int j = 0; j < 32; j++) {
        float rj = __shfl_sync(0xffffffffu, r2, j);
        h = fmaf(sW[j * 32 + l], rj, h);
    }
    out_repr[node * 32 + l] = (h >= 0.f) ? h : 0.01f * h;
}

// ---------------- launcher ----------------------------------------------------
extern "C" void kernel_launch(void* const* d_in, const int* in_sizes, int n_in,
                              void* d_out, int out_size) {
    const float* vscore    = (const float*)d_in[0];
    const float* node_repr = (const float*)d_in[1];
    const int*   eg0       = (const int*)d_in[2];
    const int*   src0      = (const int*)d_in[3];
    const int*   dst0      = (const int*)d_in[4];
    const float* rel0      = (const float*)d_in[5];
    const int*   eg1       = (const int*)d_in[6];
    const int*   src1      = (const int*)d_in[7];
    const int*   dst1      = (const int*)d_in[8];
    const float* rel1      = (const float*)d_in[9];
    const float* qemb      = (const float*)d_in[10];
    const float* remb      = (const float*)d_in[11];
    const float* Wq        = (const float*)d_in[12];
    const float* Wk        = (const float*)d_in[13];
    const float* Wlin      = (const float*)d_in[14];
    const float* blin      = (const float*)d_in[15];
    const int*   maxep     = (n_in > 16) ? (const int*)d_in[16] : nullptr;

    int N  = in_sizes[0];
    int E0 = in_sizes[2];
    int E1 = in_sizes[6];
    int Q  = in_sizes[10] / 32;

    float* out_score = (float*)d_out;
    float* out_repr  = (float*)d_out + N;

    int nb32  = (N * 32 + 255) / 256;       // elementwise over N*32
    int nbw   = (N + 7) / 8;                // warp-per-node
    int ebw0  = (E0 + 7) / 8;               // warp-per-edge
    int ebw1  = (E1 + 7) / 8;
    int ebt0  = (E0 + 255) / 256;           // thread-per-edge
    int ebt1  = (E1 + 255) / 256;

    // ---- shared precompute ----
    computeM_k<<<128, 128>>>(Wq, Wk);
    query_pre_k<<<Q, 32>>>(qemb, remb);

    // ---- layer 1 (pruned) ----
    reset_k<<<nb32, 256>>>(out_score, N);
    node_pre_k<<<nbw, 256>>>(node_repr, 0, N);
    edge_logits_k<<<ebw1, 256>>>(src1, dst1, eg1, rel1, node_repr, 0, E1);
    edge_exp_k<<<ebt1, 256>>>(src1, E1);
    ts_k<<<ebt1, 256>>>(src1, vscore, E1);
    group_off_k<<<1, 256>>>(eg1, E1, Q);
    topk_k<<<Q, 256>>>(maxep);
    scatter1_k<<<ebw1, 256>>>(src1, dst1, node_repr, vscore, out_score);
    repr_upd_k<<<nb32, 256>>>(node_repr, N);

    // ---- layer 0 (no pruning) ----
    reset_k<<<nb32, 256>>>(nullptr, N);
    node_pre_k<<<nbw, 256>>>(nullptr, 1, N);
    edge_logits_k<<<ebw0, 256>>>(src0, dst0, eg0, rel0, nullptr, 1, E0);
    edge_exp_k<<<ebt0, 256>>>(src0, E0);
    scatter0_k<<<ebw0, 256>>>(src0, dst0, E0);

    // ---- bypass_forward ----
    final_k<<<nbw, 256>>>(Wlin, blin, out_repr, N);
}

// round 2
// speedup vs baseline: 2.1885x; 2.1885x over previous
#include <cuda_runtime.h>

// ---------------- problem-size capacities (fixed by dataset) ----------------
static const int NMAX  = 100000;   // nodes
static const int EMAX  = 500000;   // edges per layer
static const int QMAXC = 128;      // queries

// ---------------- device scratch (static; no allocation) --------------------
__device__ float    dM[128 * 128];          // M = Wq^T @ Wk
__device__ float    dGx[QMAXC * 32];
__device__ float    dGy[QMAXC * 32];
__device__ float    dGrel[QMAXC * 32];
__device__ float    dCq[QMAXC];
__device__ float    dZ[NMAX * 32];          // M00 @ repr   (dst side)
__device__ float    dP[NMAX * 32];          // M01^T @ repr (src side)
__device__ float    dT[NMAX * 32];          // M10 @ repr   (dst side)
__device__ float    dRepr[NMAX * 32];       // repr_ after layer-1 update
__device__ float    dAgg[NMAX * 32];        // segment-sum accumulator
__device__ float    dLogits[EMAX];          // quad term, then full logit
__device__ float    dEx[EMAX];              // exp(logit-max), then normalized w
__device__ unsigned dTsEnc[EMAX];
__device__ unsigned dNodeMax[NMAX];
__device__ float    dNodeSum[NMAX];
__device__ int      dOff[QMAXC + 1];
__device__ int      dKlist[EMAX];
__device__ int      dKcount;

// ---------------- helpers ----------------------------------------------------
__device__ __forceinline__ unsigned encf(float f) {
    unsigned u = __float_as_uint(f);
    return (u & 0x80000000u) ? ~u : (u | 0x80000000u);
}
__device__ __forceinline__ float decf(unsigned e) {
    unsigned u = (e & 0x80000000u) ? (e & 0x7FFFFFFFu) : ~e;
    return __uint_as_float(u);
}
__device__ __forceinline__ unsigned long long packf2(float lo, float hi) {
    unsigned long long r;
    asm("mov.b64 %0, {%1, %2};" : "=l"(r) : "f"(lo), "f"(hi));
    return r;
}
__device__ __forceinline__ void unpackf2(unsigned long long v, float& lo, float& hi) {
    asm("mov.b64 {%0, %1}, %2;" : "=f"(lo), "=f"(hi) : "l"(v));
}
__device__ __forceinline__ unsigned long long fmaf2(unsigned long long a, unsigned long long b,
                                                    unsigned long long c) {
    unsigned long long d;
    asm("fma.rn.f32x2 %0, %1, %2, %3;" : "=l"(d) : "l"(a), "l"(b), "l"(c));
    return d;
}
__device__ __forceinline__ void red4(float* p, float a, float b, float c, float d) {
    asm volatile("red.global.v4.f32.add [%0], {%1, %2, %3, %4};"
                 :: "l"(p), "f"(a), "f"(b), "f"(c), "f"(d) : "memory");
}

// ---------------- kernels -----------------------------------------------------

// M[i][j] = sum_o Wq[o][i] * Wk[o][j]
__global__ void computeM_k(const float* __restrict__ Wq, const float* __restrict__ Wk) {
    int i = blockIdx.x, j = threadIdx.x;
    float acc = 0.f;
    #pragma unroll 8
    for (int o = 0; o < 128; o++)
        acc = fmaf(Wq[o * 128 + i], Wk[o * 128 + j], acc);
    dM[i * 128 + j] = acc;
}

// Per-query precompute. One block (32 threads) per query.
__global__ void query_pre_k(const float* __restrict__ qemb, const float* __restrict__ remb) {
    int q = blockIdx.x, d = threadIdx.x;
    __shared__ float qv[32], rv[32];
    qv[d] = qemb[q * 32 + d];
    rv[d] = remb[q * 32 + d];
    __syncwarp();
    float gx = 0.f, gy = 0.f, gr = 0.f;
    for (int k = 0; k < 32; k++) {
        float qk = qv[k], rk = rv[k];
        gx = fmaf(dM[d * 128 + 64 + k], qk, gx);
        gx = fmaf(dM[d * 128 + 96 + k], rk, gx);
        gy = fmaf(dM[(64 + k) * 128 + d], qk, gy);
        gy = fmaf(dM[(96 + k) * 128 + d], rk, gy);
        gr = fmaf(dM[(32 + d) * 128 + 64 + k], qk, gr);
        gr = fmaf(dM[(32 + d) * 128 + 96 + k], rk, gr);
        gr = fmaf(dM[(64 + k) * 128 + 32 + d], qk, gr);
        gr = fmaf(dM[(96 + k) * 128 + 32 + d], rk, gr);
    }
    dGx[q * 32 + d] = gx;
    dGy[q * 32 + d] = gy;
    dGrel[q * 32 + d] = gr;
    float c = 0.f;
    for (int l = 0; l < 32; l++) {
        c = fmaf(qv[d], fmaf(dM[(64 + d) * 128 + 64 + l], qv[l], dM[(64 + d) * 128 + 96 + l] * rv[l]), c);
        c = fmaf(rv[d], fmaf(dM[(96 + d) * 128 + 64 + l], qv[l], dM[(96 + d) * 128 + 96 + l] * rv[l]), c);
    }
    for (int off = 16; off; off >>= 1) c += __shfl_xor_sync(0xffffffffu, c, off);
    if (d == 0) dCq[q] = c;
}

// Reset accumulators.
__global__ void reset_k(float* score_out, int N) {
    int i = blockIdx.x * blockDim.x + threadIdx.x;
    if (i < N * 32) dAgg[i] = 0.f;
    if (i < N) {
        dNodeMax[i] = 0u;
        dNodeSum[i] = 0.f;
        if (score_out) score_out[i] = 0.f;
    }
    if (i == 0) dKcount = 0;
}

// Per-node z/p/t precompute. Thread-per-node, W broadcast from shared, staged IO.
__global__ void __launch_bounds__(256) node_pre2_k(const float* repr_ext, int use_internal, int N) {
    __shared__ __align__(16) float sW[96 * 32];
    __shared__ float sR[256 * 33];
    const float* repr = use_internal ? dRepr : repr_ext;
    int t = threadIdx.x;
    // Combined weight rows: [0,32)=M00, [32,64)=M01^T, [64,96)=M10
    for (int i = t; i < 96 * 32; i += 256) {
        int o = i >> 5, k = i & 31;
        float v;
        if (o < 32)      v = dM[o * 128 + k];
        else if (o < 64) v = dM[k * 128 + 32 + (o - 32)];
        else             v = dM[(32 + (o - 64)) * 128 + k];
        sW[i] = v;
    }
    int base = blockIdx.x * 256;
    for (int i = t; i < 256 * 32; i += 256) {
        int n = base + (i >> 5);
        sR[(i >> 5) * 33 + (i & 31)] = (n < N) ? repr[n * 32 + (i & 31)] : 0.f;
    }
    __syncthreads();
    float re[32];
    #pragma unroll
    for (int k = 0; k < 32; k++) re[k] = sR[t * 33 + k];

    for (int c = 0; c < 3; c++) {
        const float4* Wv = reinterpret_cast<const float4*>(sW + c * 1024);
        float acc[32];
        #pragma unroll
        for (int o = 0; o < 32; o++) {
            float a = 0.f;
            #pragma unroll
            for (int k4 = 0; k4 < 8; k4++) {
                float4 m = Wv[o * 8 + k4];
                a = fmaf(m.x, re[4 * k4 + 0], a);
                a = fmaf(m.y, re[4 * k4 + 1], a);
                a = fmaf(m.z, re[4 * k4 + 2], a);
                a = fmaf(m.w, re[4 * k4 + 3], a);
            }
            acc[o] = a;
        }
        __syncthreads();
        #pragma unroll
        for (int o = 0; o < 32; o++) sR[t * 33 + o] = acc[o];
        __syncthreads();
        float* out = (c == 0) ? dZ : (c == 1) ? dP : dT;
        for (int i = t; i < 256 * 32; i += 256) {
            int n = base + (i >> 5);
            if (n < N) out[n * 32 + (i & 31)] = sR[(i >> 5) * 33 + (i & 31)];
        }
        __syncthreads();
    }
}

// Quadratic rel^T M11 rel. Thread handles 2 edges via packed f32x2.
__global__ void __launch_bounds__(256) quad_k(const float* __restrict__ rel, int E) {
    __shared__ __align__(16) unsigned long long sM2[1024];   // {m,m} packed M11[j][k]
    __shared__ float sRe[256 * 33];
    int t = threadIdx.x;
    for (int i = t; i < 1024; i += 256) {
        float m = dM[(32 + (i >> 5)) * 128 + 32 + (i & 31)];
        sM2[i] = packf2(m, m);
    }
    int base = blockIdx.x * 512;
    // stage A edges [base, base+256)
    for (int i = t; i < 256 * 32; i += 256) {
        int e = base + (i >> 5);
        sRe[(i >> 5) * 33 + (i & 31)] = (e < E) ? rel[(size_t)e * 32 + (i & 31)] : 0.f;
    }
    __syncthreads();
    float reA[32];
    #pragma unroll
    for (int k = 0; k < 32; k++) reA[k] = sRe[t * 33 + k];
    __syncthreads();
    // stage B edges [base+256, base+512)
    for (int i = t; i < 256 * 32; i += 256) {
        int e = base + 256 + (i >> 5);
        sRe[(i >> 5) * 33 + (i & 31)] = (e < E) ? rel[(size_t)e * 32 + (i & 31)] : 0.f;
    }
    __syncthreads();
    unsigned long long re2[32];
    #pragma unroll
    for (int k = 0; k < 32; k++) re2[k] = packf2(reA[k], sRe[t * 33 + k]);

    unsigned long long w2 = packf2(0.f, 0.f);
    #pragma unroll 4
    for (int j = 0; j < 32; j++) {
        unsigned long long v2 = packf2(0.f, 0.f);
        #pragma unroll
        for (int k = 0; k < 32; k++)
            v2 = fmaf2(sM2[j * 32 + k], re2[k], v2);
        w2 = fmaf2(re2[j], v2, w2);
    }
    float wA, wB;
    unpackf2(w2, wA, wB);
    int eA = base + t, eB = base + 256 + t;
    if (eA < E) dLogits[eA] = wA;
    if (eB < E) dLogits[eB] = wB;
}

// Linear logit terms. One warp per edge; adds quad term from dLogits.
__global__ void edge_lin_k(const int* __restrict__ src, const int* __restrict__ dst,
                           const int* __restrict__ eg, const float* __restrict__ rel,
                           const float* repr_ext, int use_internal, int E) {
    const float* repr = use_internal ? dRepr : repr_ext;
    int e = (int)((blockIdx.x * (unsigned)blockDim.x + threadIdx.x) >> 5);
    int j = threadIdx.x & 31;
    if (e >= E) return;
    int s = __ldg(&src[e]), d = __ldg(&dst[e]), g = __ldg(&eg[e]);
    float x  = repr[s * 32 + j];
    float y  = repr[d * 32 + j];
    float zz = dZ[d * 32 + j];
    float pp = dP[s * 32 + j];
    float tt = dT[d * 32 + j];
    float re = __ldg(&rel[(size_t)e * 32 + j]);
    float part = x * (zz + dGx[g * 32 + j]) + y * dGy[g * 32 + j]
               + re * (pp + tt + dGrel[g * 32 + j]);
    #pragma unroll
    for (int off = 16; off; off >>= 1) part += __shfl_xor_sync(0xffffffffu, part, off);
    if (j == 0) {
        float logit = part + dLogits[e] + dCq[g];
        dLogits[e] = logit;
        atomicMax(&dNodeMax[s], encf(logit));
    }
}

// exp(logit - max) + per-src sum. Thread per edge.
__global__ void edge_exp_k(const int* __restrict__ src, int E) {
    int e = blockIdx.x * blockDim.x + threadIdx.x;
    if (e >= E) return;
    int s = src[e];
    float m = decf(dNodeMax[s]);
    float ex = expf(dLogits[e] - m);
    dEx[e] = ex;
    atomicAdd(&dNodeSum[s], ex);
}

// Normalize w and write encoded target score (layer 1).
__global__ void ts_k(const int* __restrict__ src, const float* __restrict__ vscore, int E) {
    int e = blockIdx.x * blockDim.x + threadIdx.x;
    if (e >= E) return;
    int s = src[e];
    float w = dEx[e] / dNodeSum[s];
    dEx[e] = w;
    dTsEnc[e] = __float_as_uint(w * vscore[s]);
}

// Normalize w only (layer 0).
__global__ void edge_w_k(const int* __restrict__ src, int E) {
    int e = blockIdx.x * blockDim.x + threadIdx.x;
    if (e >= E) return;
    dEx[e] = dEx[e] / dNodeSum[src[e]];
}

// eg-group offsets by binary search.
__global__ void group_off_k(const int* __restrict__ eg, int E, int Q) {
    int g = blockIdx.x * blockDim.x + threadIdx.x;
    if (g > Q) return;
    int lo = 0, hi = E;
    while (lo < hi) {
        int mid = (lo + hi) >> 1;
        if (eg[mid] < g) lo = mid + 1; else hi = mid;
    }
    dOff[g] = lo;
}

// Per-group top-k, stable tie-break (value desc, index asc).
__global__ void topk_k(const int* maxe) {
    int g = blockIdx.x;
    int lo = dOff[g], hi = dOff[g + 1];
    int len = hi - lo;
    if (len <= 0) return;
    int K = maxe ? maxe[0] : 500;
    if (K > len) K = len;

    __shared__ int hist[256];
    __shared__ int s_selbin, s_rem;
    unsigned prefix = 0u;
    int remaining = K;
    for (int shift = 24; shift >= 0; shift -= 8) {
        unsigned mask_hi = (shift == 24) ? 0u : (0xFFFFFFFFu << (shift + 8));
        for (int i = threadIdx.x; i < 256; i += blockDim.x) hist[i] = 0;
        __syncthreads();
        for (int i = lo + threadIdx.x; i < hi; i += blockDim.x) {
            unsigned v = dTsEnc[i];
            if ((v & mask_hi) == prefix) atomicAdd(&hist[(v >> shift) & 255], 1);
        }
        __syncthreads();
        if (threadIdx.x == 0) {
            int cum = 0, b = 255;
            for (; b > 0; b--) { cum += hist[b]; if (cum >= remaining) break; }
            if (cum < remaining) cum += hist[0];
            s_selbin = b;
            s_rem = remaining - (cum - hist[b]);
        }
        __syncthreads();
        prefix |= ((unsigned)s_selbin) << shift;
        remaining = s_rem;
        __syncthreads();
    }
    unsigned T = prefix;
    int quota_eq = remaining;

    __shared__ int warp_cnt[8];
    __shared__ int s_running;
    if (threadIdx.x == 0) s_running = 0;
    __syncthreads();
    for (int base = lo; base < hi; base += blockDim.x) {
        int i = base + (int)threadIdx.x;
        bool valid = i < hi;
        unsigned v = valid ? dTsEnc[i] : 0u;
        bool gt = valid && (v > T);
        bool eq = valid && (v == T);
        unsigned bal = __ballot_sync(0xffffffffu, eq);
        int lane = threadIdx.x & 31, wrp = threadIdx.x >> 5;
        int myrank = __popc(bal & ((1u << lane) - 1u));
        if (lane == 0) warp_cnt[wrp] = __popc(bal);
        __syncthreads();
        int woff = 0, chunk_tot = 0;
        #pragma unroll
        for (int ww = 0; ww < 8; ww++) {
            int c = warp_cnt[ww];
            if (ww < wrp) woff += c;
            chunk_tot += c;
        }
        int rank = s_running + woff + myrank;
        bool keep = gt || (eq && rank < quota_eq);
        if (keep) {
            int pos = atomicAdd(&dKcount, 1);
            dKlist[pos] = i;
        }
        __syncthreads();
        if (threadIdx.x == 0) s_running += chunk_tot;
        __syncthreads();
    }
}

// Layer-1 scatter over kept edges. 8 threads per kept edge, red.v4.
__global__ void scatter1_k(const int* __restrict__ src, const int* __restrict__ dst,
                           const float* __restrict__ node_repr, const float* __restrict__ vscore,
                           float* __restrict__ score_out) {
    unsigned gid = blockIdx.x * (unsigned)blockDim.x + threadIdx.x;
    int i = (int)(gid >> 3), q = (int)(gid & 7);
    if (i >= dKcount) return;
    int e = dKlist[i];
    int s = src[e], d = dst[e];
    float w = dEx[e];
    float4 v = *reinterpret_cast<const float4*>(&node_repr[s * 32 + q * 4]);
    red4(&dAgg[d * 32 + q * 4], w * v.x, w * v.y, w * v.z, w * v.w);
    if (q == 0) atomicAdd(&score_out[d], w * vscore[s]);
}

// repr_ = 0.8*agg + 0.2*node_repr
__global__ void repr_upd_k(const float* __restrict__ node_repr, int N) {
    int i = blockIdx.x * blockDim.x + threadIdx.x;
    if (i < N * 32) dRepr[i] = fmaf(0.8f, dAgg[i], 0.2f * node_repr[i]);
}

// Layer-0 scatter over all edges. 8 threads per edge, red.v4.
__global__ void scatter0_k(const int* __restrict__ src, const int* __restrict__ dst, int E) {
    unsigned gid = blockIdx.x * (unsigned)blockDim.x + threadIdx.x;
    int e = (int)(gid >> 3), q = (int)(gid & 7);
    if (e >= E) return;
    int s = src[e], d = dst[e];
    float w = dEx[e];
    float4 v = *reinterpret_cast<const float4*>(&dRepr[s * 32 + q * 4]);
    red4(&dAgg[d * 32 + q * 4], w * v.x, w * v.y, w * v.z, w * v.w);
}

// Final bypass: r2 = 0.8*agg0 + 0.2*repr_; out = LeakyReLU(Wlin r2 + blin).
__global__ void __launch_bounds__(256) final2_k(const float* __restrict__ Wlin,
                                                const float* __restrict__ blin,
                                                float* __restrict__ out_repr, int N) {
    __shared__ __align__(16) float sW[1024];   // Wlin row-major [l][j]
    __shared__ float sR[256 * 33];
    __shared__ float sB[32];
    int t = threadIdx.x;
    for (int i = t; i < 1024; i += 256) sW[i] = Wlin[i];
    if (t < 32) sB[t] = blin[t];
    int base = blockIdx.x * 256;
    for (int i = t; i < 256 * 32; i += 256) {
        int n = base + (i >> 5);
        float v = 0.f;
        if (n < N) {
            int idx = n * 32 + (i & 31);
            v = fmaf(0.8f, dAgg[idx], 0.2f * dRepr[idx]);
        }
        sR[(i >> 5) * 33 + (i & 31)] = v;
    }
    __syncthreads();
    float re[32];
    #pragma unroll
    for (int k = 0; k < 32; k++) re[k] = sR[t * 33 + k];
    const float4* Wv = reinterpret_cast<const float4*>(sW);
    float acc[32];
    #pragma unroll
    for (int l = 0; l < 32; l++) {
        float a = sB[l];
        #pragma unroll
        for (int k4 = 0; k4 < 8; k4++) {
            float4 m = Wv[l * 8 + k4];
            a = fmaf(m.x, re[4 * k4 + 0], a);
            a = fmaf(m.y, re[4 * k4 + 1], a);
            a = fmaf(m.z, re[4 * k4 + 2], a);
            a = fmaf(m.w, re[4 * k4 + 3], a);
        }
        acc[l] = (a >= 0.f) ? a : 0.01f * a;
    }
    __syncthreads();
    #pragma unroll
    for (int l = 0; l < 32; l++) sR[t * 33 + l] = acc[l];
    __syncthreads();
    for (int i = t; i < 256 * 32; i += 256) {
        int n = base + (i >> 5);
        if (n < N) out_repr[n * 32 + (i & 31)] = sR[(i >> 5) * 33 + (i & 31)];
    }
}

// ---------------- launcher ----------------------------------------------------
extern "C" void kernel_launch(void* const* d_in, const int* in_sizes, int n_in,
                              void* d_out, int out_size) {
    const float* vscore    = (const float*)d_in[0];
    const float* node_repr = (const float*)d_in[1];
    const int*   eg0       = (const int*)d_in[2];
    const int*   src0      = (const int*)d_in[3];
    const int*   dst0      = (const int*)d_in[4];
    const float* rel0      = (const float*)d_in[5];
    const int*   eg1       = (const int*)d_in[6];
    const int*   src1      = (const int*)d_in[7];
    const int*   dst1      = (const int*)d_in[8];
    const float* rel1      = (const float*)d_in[9];
    const float* qemb      = (const float*)d_in[10];
    const float* remb      = (const float*)d_in[11];
    const float* Wq        = (const float*)d_in[12];
    const float* Wk        = (const float*)d_in[13];
    const float* Wlin      = (const float*)d_in[14];
    const float* blin      = (const float*)d_in[15];
    const int*   maxep     = (n_in > 16) ? (const int*)d_in[16] : nullptr;

    int N  = in_sizes[0];
    int E0 = in_sizes[2];
    int E1 = in_sizes[6];
    int Q  = in_sizes[10] / 32;

    float* out_score = (float*)d_out;
    float* out_repr  = (float*)d_out + N;

    int nb32 = (N * 32 + 255) / 256;       // elementwise over N*32
    int nbn  = (N + 255) / 256;            // thread-per-node
    int ebq0 = (E0 + 511) / 512;           // quad blocks
    int ebq1 = (E1 + 511) / 512;
    int ebw0 = (E0 + 7) / 8;               // warp-per-edge
    int ebw1 = (E1 + 7) / 8;
    int ebt0 = (E0 + 255) / 256;           // thread-per-edge
    int ebt1 = (E1 + 255) / 256;
    int ebs0 = (E0 * 8 + 255) / 256;       // 8 threads/edge
    int ebs1 = (E1 * 8 + 255) / 256;

    // ---- shared precompute ----
    computeM_k<<<128, 128>>>(Wq, Wk);
    query_pre_k<<<Q, 32>>>(qemb, remb);

    // ---- layer 1 (pruned) ----
    reset_k<<<nb32, 256>>>(out_score, N);
    node_pre2_k<<<nbn, 256>>>(node_repr, 0, N);
    quad_k<<<ebq1, 256>>>(rel1, E1);
    edge_lin_k<<<ebw1, 256>>>(src1, dst1, eg1, rel1, node_repr, 0, E1);
    edge_exp_k<<<ebt1, 256>>>(src1, E1);
    ts_k<<<ebt1, 256>>>(src1, vscore, E1);
    group_off_k<<<1, 256>>>(eg1, E1, Q);
    topk_k<<<Q, 256>>>(maxep);
    scatter1_k<<<ebs1, 256>>>(src1, dst1, node_repr, vscore, out_score);
    repr_upd_k<<<nb32, 256>>>(node_repr, N);

    // ---- layer 0 (no pruning) ----
    reset_k<<<nb32, 256>>>(nullptr, N);
    node_pre2_k<<<nbn, 256>>>(nullptr, 1, N);
    quad_k<<<ebq0, 256>>>(rel0, E0);
    edge_lin_k<<<ebw0, 256>>>(src0, dst0, eg0, rel0, nullptr, 1, E0);
    edge_exp_k<<<ebt0, 256>>>(src0, E0);
    edge_w_k<<<ebt0, 256>>>(src0, E0);
    scatter0_k<<<ebs0, 256>>>(src0, dst0, E0);

    // ---- bypass_forward ----
    final2_k<<<nbn, 256>>>(Wlin, blin, out_repr, N);
}

// round 3
// speedup vs baseline: 2.4205x; 1.1060x over previous
#include <cuda_runtime.h>

// ---------------- problem-size capacities (fixed by dataset) ----------------
static const int NMAX  = 100000;
static const int EMAX  = 500000;
static const int QMAXC = 128;

// ---------------- device scratch (static; no allocation) --------------------
__device__ float    dM[128 * 128];          // M = Wq^T @ Wk
__device__ float    dGx[QMAXC * 32];
__device__ float    dGy[QMAXC * 32];
__device__ float    dGrel[QMAXC * 32];
__device__ float    dCq[QMAXC];
__device__ float    dZ[NMAX * 32];
__device__ float    dP[NMAX * 32];
__device__ float    dT[NMAX * 32];
__device__ float    dRepr[NMAX * 32];
__device__ float    dAgg[NMAX * 32];
__device__ float    dLogits1[EMAX];         // layer-1: quad term, then logit
__device__ float    dLogits0[EMAX];         // layer-0: quad term, then logit
__device__ float    dEx[EMAX];
__device__ unsigned dTsEnc[EMAX];
__device__ unsigned dNodeMax[NMAX];
__device__ float    dNodeSum[NMAX];
__device__ int      dOff[QMAXC + 1];
__device__ int      dKlist[EMAX];
__device__ int      dKcount;

// ---------------- helpers ----------------------------------------------------
__device__ __forceinline__ unsigned encf(float f) {
    unsigned u = __float_as_uint(f);
    return (u & 0x80000000u) ? ~u : (u | 0x80000000u);
}
__device__ __forceinline__ float decf(unsigned e) {
    unsigned u = (e & 0x80000000u) ? (e & 0x7FFFFFFFu) : ~e;
    return __uint_as_float(u);
}
__device__ __forceinline__ unsigned long long packf2(float lo, float hi) {
    unsigned long long r;
    asm("mov.b64 %0, {%1, %2};" : "=l"(r) : "f"(lo), "f"(hi));
    return r;
}
__device__ __forceinline__ void unpackf2(unsigned long long v, float& lo, float& hi) {
    asm("mov.b64 {%0, %1}, %2;" : "=f"(lo), "=f"(hi) : "l"(v));
}
__device__ __forceinline__ unsigned long long fmaf2(unsigned long long a, unsigned long long b,
                                                    unsigned long long c) {
    unsigned long long d;
    asm("fma.rn.f32x2 %0, %1, %2, %3;" : "=l"(d) : "l"(a), "l"(b), "l"(c));
    return d;
}
__device__ __forceinline__ void red4(float* p, float a, float b, float c, float d) {
    asm volatile("red.global.v4.f32.add [%0], {%1, %2, %3, %4};"
                 :: "l"(p), "f"(a), "f"(b), "f"(c), "f"(d) : "memory");
}

// ---------------- prep: computeM + query_pre + group_off + resets -------------
// block layout: [0,128) computeM rows | [128,128+Q) query_pre | [128+Q] group_off
//               | rest: reset arrays
__global__ void __launch_bounds__(128) prep_k(const float* __restrict__ Wq,
                                              const float* __restrict__ Wk,
                                              const float* __restrict__ qemb,
                                              const float* __restrict__ remb,
                                              const int* __restrict__ eg1,
                                              float* __restrict__ score_out,
                                              int N, int E1, int Q) {
    int b = blockIdx.x, t = threadIdx.x;
    if (b < 128) {
        // M[i][j] = sum_o Wq[o][i] * Wk[o][j]
        int i = b, j = t;
        float acc = 0.f;
        #pragma unroll 8
        for (int o = 0; o < 128; o++)
            acc = fmaf(__ldg(&Wq[o * 128 + i]), __ldg(&Wk[o * 128 + j]), acc);
        dM[i * 128 + j] = acc;
        return;
    }
    if (b < 128 + Q) {
        if (t >= 32) return;
        int q = b - 128, d = t;
        __shared__ float qv[32], rv[32];
        qv[d] = qemb[q * 32 + d];
        rv[d] = remb[q * 32 + d];
        __syncwarp();
        // NOTE: dM written by other blocks in this grid?  No — computeM is in the
        // SAME kernel; cross-block dependency is illegal.  So query_pre must read
        // Wq/Wk-derived M... we recompute needed dM entries?  Too costly.
        // Instead: compute the needed M entries on the fly from Wq/Wk columns.
        // g-vectors only need M blocks with q/r columns (cols 64..127) and rows
        // 0..127; each entry M[a][b] = sum_o Wq[o][a]*Wk[o][b] (128 MACs).
        // That is 128*... too expensive per thread.  Fallback: this block
        // computes its OWN copy of the required M entries via shared staging.
        // Simpler: stage Wq, Wk columns and compute directly:
        //   gx_d  = sum_c M[d][64+c] qv[c] + M[d][96+c] rv[c]
        //         = sum_o Wq[o][d] * (sum_c Wk[o][64+c] qv[c] + Wk[o][96+c] rv[c])
        // Define u[o] = Wk[o][64:96]·qv + Wk[o][96:128]·rv   (for gx, c-term row side)
        //        v[o] = Wq[o][64:96]·qv + Wq[o][96:128]·rv   (for gy)
        // gx_d = sum_o Wq[o][d]   * u[o]
        // gy_d = sum_o Wk[o][d]   * v[o]
        // grel_d = sum_o Wq[o][32+d]*u[o] + Wk[o][32+d]*v[o]
        // c    = sum_o u[o]*v[o]
        __shared__ float su[128], sv[128];
        for (int o = d; o < 128; o += 32) {
            float uu = 0.f, vv = 0.f;
            #pragma unroll
            for (int c = 0; c < 32; c++) {
                uu = fmaf(__ldg(&Wk[o * 128 + 64 + c]), qv[c], uu);
                uu = fmaf(__ldg(&Wk[o * 128 + 96 + c]), rv[c], uu);
                vv = fmaf(__ldg(&Wq[o * 128 + 64 + c]), qv[c], vv);
                vv = fmaf(__ldg(&Wq[o * 128 + 96 + c]), rv[c], vv);
            }
            su[o] = uu; sv[o] = vv;
        }
        __syncwarp();
        float gx = 0.f, gy = 0.f, gr = 0.f, cq = 0.f;
        for (int o = 0; o < 128; o++) {
            float uo = su[o], vo = sv[o];
            gx = fmaf(__ldg(&Wq[o * 128 + d]), uo, gx);
            gy = fmaf(__ldg(&Wk[o * 128 + d]), vo, gy);
            gr = fmaf(__ldg(&Wq[o * 128 + 32 + d]), uo, gr);
            gr = fmaf(__ldg(&Wk[o * 128 + 32 + d]), vo, gr);
            if (d == 0) cq = fmaf(uo, vo, cq);
        }
        dGx[q * 32 + d] = gx;
        dGy[q * 32 + d] = gy;
        dGrel[q * 32 + d] = gr;
        if (d == 0) dCq[q] = cq;
        return;
    }
    if (b == 128 + Q) {
        for (int g = t; g <= Q; g += 128) {
            int lo = 0, hi = E1;
            while (lo < hi) {
                int mid = (lo + hi) >> 1;
                if (eg1[mid] < g) lo = mid + 1; else hi = mid;
            }
            dOff[g] = lo;
        }
        return;
    }
    int i = (b - (129 + Q)) * 128 + t;
    if (i < N * 32) dAgg[i] = 0.f;
    if (i < N) {
        dNodeMax[i] = 0u;
        dNodeSum[i] = 0.f;
        score_out[i] = 0.f;
    }
    if (i == 0) dKcount = 0;
}

// ---------------- node precompute: z/p/t (+ optional fused repr update) -------
// mode 0: repr = repr_ext (layer 1 input)
// mode 1: repr = 0.8*dAgg + 0.2*node_repr; writes dRepr, zeroes dAgg/max/sum
__global__ void __launch_bounds__(128, 6) node_pre3_k(const float* __restrict__ repr_ext,
                                                      int mode, int N) {
    __shared__ __align__(16) float sW[96 * 32];
    __shared__ float sR[128 * 33];
    int t = threadIdx.x;
    for (int i = t; i < 96 * 32; i += 128) {
        int o = i >> 5, k = i & 31;
        float v;
        if (o < 32)      v = dM[o * 128 + k];
        else if (o < 64) v = dM[k * 128 + 32 + (o - 32)];
        else             v = dM[(32 + (o - 64)) * 128 + k];
        sW[i] = v;
    }
    int base = blockIdx.x * 128;
    if (mode == 0) {
        for (int i = t; i < 128 * 32; i += 128) {
            int n = base + (i >> 5);
            sR[(i >> 5) * 33 + (i & 31)] = (n < N) ? repr_ext[n * 32 + (i & 31)] : 0.f;
        }
    } else {
        for (int i = t; i < 128 * 32; i += 128) {
            int n = base + (i >> 5);
            float v = 0.f;
            if (n < N) {
                int g = n * 32 + (i & 31);
                v = fmaf(0.8f, dAgg[g], 0.2f * repr_ext[g]);
                dRepr[g] = v;
                dAgg[g] = 0.f;
            }
            sR[(i >> 5) * 33 + (i & 31)] = v;
        }
        int n = base + t;
        if (n < N) { dNodeMax[n] = 0u; dNodeSum[n] = 0.f; }
    }
    __syncthreads();
    float re[32];
    #pragma unroll
    for (int k = 0; k < 32; k++) re[k] = sR[t * 33 + k];

    const float4* Wv = reinterpret_cast<const float4*>(sW);
    bool live = (base + t) < N;
    #pragma unroll 1
    for (int c = 0; c < 3; c++) {
        float* out = (c == 0) ? dZ : (c == 1) ? dP : dT;
        #pragma unroll 1
        for (int h = 0; h < 2; h++) {
            float acc[16];
            #pragma unroll
            for (int o = 0; o < 16; o++) {
                int row = c * 32 + h * 16 + o;
                float a = 0.f;
                #pragma unroll
                for (int k4 = 0; k4 < 8; k4++) {
                    float4 m = Wv[row * 8 + k4];
                    a = fmaf(m.x, re[4 * k4 + 0], a);
                    a = fmaf(m.y, re[4 * k4 + 1], a);
                    a = fmaf(m.z, re[4 * k4 + 2], a);
                    a = fmaf(m.w, re[4 * k4 + 3], a);
                }
                acc[o] = a;
            }
            __syncthreads();
            if (live) {
                #pragma unroll
                for (int o = 0; o < 16; o++) sR[t * 17 + o] = acc[o];
            }
            __syncthreads();
            for (int i = t; i < 128 * 16; i += 128) {
                int n = base + (i >> 4);
                if (n < N) out[n * 32 + h * 16 + (i & 15)] = sR[(i >> 4) * 17 + (i & 15)];
            }
        }
    }
}

// ---------------- quadratic term, both layers, triangular form ----------------
__global__ void __launch_bounds__(256) quad_k(const float* __restrict__ rel1,
                                              const float* __restrict__ rel0,
                                              int E1, int E0, int nq1) {
    __shared__ __align__(16) unsigned long long sTri[528];
    __shared__ float sRe[256 * 33];
    int t = threadIdx.x;
    // triangle coefficients: row j: diag M11[j][j], then M11[j][k]+M11[k][j] (k>j)
    for (int i = t; i < 528; i += 256) {
        int j = 0, off = 0;
        while (off + (32 - j) <= i) { off += 32 - j; j++; }
        int k = j + (i - off);
        float v = (k == j) ? dM[(32 + j) * 128 + 32 + j]
                           : dM[(32 + j) * 128 + 32 + k] + dM[(32 + k) * 128 + 32 + j];
        sTri[i] = packf2(v, v);
    }
    bool l1 = blockIdx.x < nq1;
    const float* rel = l1 ? rel1 : rel0;
    float* out = l1 ? dLogits1 : dLogits0;
    int E = l1 ? E1 : E0;
    int base = (l1 ? blockIdx.x : blockIdx.x - nq1) * 512;

    for (int i = t; i < 256 * 32; i += 256) {
        int e = base + (i >> 5);
        sRe[(i >> 5) * 33 + (i & 31)] = (e < E) ? rel[(size_t)e * 32 + (i & 31)] : 0.f;
    }
    __syncthreads();
    float reA[32];
    #pragma unroll
    for (int k = 0; k < 32; k++) reA[k] = sRe[t * 33 + k];
    __syncthreads();
    for (int i = t; i < 256 * 32; i += 256) {
        int e = base + 256 + (i >> 5);
        sRe[(i >> 5) * 33 + (i & 31)] = (e < E) ? rel[(size_t)e * 32 + (i & 31)] : 0.f;
    }
    __syncthreads();
    unsigned long long re2[32];
    #pragma unroll
    for (int k = 0; k < 32; k++) re2[k] = packf2(reA[k], sRe[t * 33 + k]);

    const unsigned long long z2 = packf2(0.f, 0.f);
    unsigned long long w2 = z2;
    #pragma unroll
    for (int j = 0; j < 32; j++) {
        const int off = 32 * j - (j * (j - 1)) / 2;
        unsigned long long v2 = fmaf2(sTri[off], re2[j], z2);
        #pragma unroll
        for (int k = j + 1; k < 32; k++)
            v2 = fmaf2(sTri[off + (k - j)], re2[k], v2);
        w2 = fmaf2(re2[j], v2, w2);
    }
    float wA, wB;
    unpackf2(w2, wA, wB);
    int eA = base + t, eB = base + 256 + t;
    if (eA < E) out[eA] = wA;
    if (eB < E) out[eB] = wB;
}

// ---------------- linear logit terms, warp per edge ---------------------------
__global__ void edge_lin_k(const int* __restrict__ src, const int* __restrict__ dst,
                           const int* __restrict__ eg, const float* __restrict__ rel,
                           const float* repr_ext, int use_internal, int layer1, int E) {
    const float* repr = use_internal ? dRepr : repr_ext;
    float* lgt = layer1 ? dLogits1 : dLogits0;
    int e = (int)((blockIdx.x * (unsigned)blockDim.x + threadIdx.x) >> 5);
    int j = threadIdx.x & 31;
    if (e >= E) return;
    int s = __ldg(&src[e]), d = __ldg(&dst[e]), g = __ldg(&eg[e]);
    float x  = repr[s * 32 + j];
    float y  = repr[d * 32 + j];
    float zz = dZ[d * 32 + j];
    float pp = dP[s * 32 + j];
    float tt = dT[d * 32 + j];
    float re = __ldg(&rel[(size_t)e * 32 + j]);
    float part = x * (zz + dGx[g * 32 + j]) + y * dGy[g * 32 + j]
               + re * (pp + tt + dGrel[g * 32 + j]);
    #pragma unroll
    for (int off = 16; off; off >>= 1) part += __shfl_xor_sync(0xffffffffu, part, off);
    if (j == 0) {
        float logit = part + lgt[e] + dCq[g];
        lgt[e] = logit;
        atomicMax(&dNodeMax[s], encf(logit));
    }
}

// ---------------- exp(logit - max) + per-src sum -------------------------------
__global__ void edge_exp_k(const int* __restrict__ src, int layer1, int E) {
    int e = blockIdx.x * blockDim.x + threadIdx.x;
    if (e >= E) return;
    int s = src[e];
    float m = decf(dNodeMax[s]);
    float lg = layer1 ? dLogits1[e] : dLogits0[e];
    float ex = __expf(lg - m);
    dEx[e] = ex;
    atomicAdd(&dNodeSum[s], ex);
}

// ---------------- normalize + encoded target score (layer 1) ------------------
__global__ void ts_k(const int* __restrict__ src, const float* __restrict__ vscore, int E) {
    int e = blockIdx.x * blockDim.x + threadIdx.x;
    if (e >= E) return;
    int s = src[e];
    float w = __fdividef(dEx[e], dNodeSum[s]);
    dEx[e] = w;
    dTsEnc[e] = __float_as_uint(w * vscore[s]);
}

// ---------------- per-group top-k (stable: value desc, index asc) -------------
__global__ void topk_k(const int* maxe) {
    int g = blockIdx.x;
    int lo = dOff[g], hi = dOff[g + 1];
    int len = hi - lo;
    if (len <= 0) return;
    int K = maxe ? maxe[0] : 500;
    if (K > len) K = len;

    __shared__ int hist[256];
    __shared__ int s_selbin, s_rem;
    unsigned prefix = 0u;
    int remaining = K;
    for (int shift = 24; shift >= 0; shift -= 8) {
        unsigned mask_hi = (shift == 24) ? 0u : (0xFFFFFFFFu << (shift + 8));
        for (int i = threadIdx.x; i < 256; i += blockDim.x) hist[i] = 0;
        __syncthreads();
        for (int i = lo + threadIdx.x; i < hi; i += blockDim.x) {
            unsigned v = dTsEnc[i];
            if ((v & mask_hi) == prefix) atomicAdd(&hist[(v >> shift) & 255], 1);
        }
        __syncthreads();
        if (threadIdx.x == 0) {
            int cum = 0, b = 255;
            for (; b > 0; b--) { cum += hist[b]; if (cum >= remaining) break; }
            if (cum < remaining) cum += hist[0];
            s_selbin = b;
            s_rem = remaining - (cum - hist[b]);
        }
        __syncthreads();
        prefix |= ((unsigned)s_selbin) << shift;
        remaining = s_rem;
        __syncthreads();
    }
    unsigned T = prefix;
    int quota_eq = remaining;

    __shared__ int warp_cnt[8];
    __shared__ int s_running;
    if (threadIdx.x == 0) s_running = 0;
    __syncthreads();
    for (int base = lo; base < hi; base += blockDim.x) {
        int i = base + (int)threadIdx.x;
        bool valid = i < hi;
        unsigned v = valid ? dTsEnc[i] : 0u;
        bool gt = valid && (v > T);
        bool eq = valid && (v == T);
        unsigned bal = __ballot_sync(0xffffffffu, eq);
        int lane = threadIdx.x & 31, wrp = threadIdx.x >> 5;
        int myrank = __popc(bal & ((1u << lane) - 1u));
        if (lane == 0) warp_cnt[wrp] = __popc(bal);
        __syncthreads();
        int woff = 0, chunk_tot = 0;
        #pragma unroll
        for (int ww = 0; ww < 8; ww++) {
            int c = warp_cnt[ww];
            if (ww < wrp) woff += c;
            chunk_tot += c;
        }
        int rank = s_running + woff + myrank;
        bool keep = gt || (eq && rank < quota_eq);
        if (keep) {
            int pos = atomicAdd(&dKcount, 1);
            dKlist[pos] = i;
        }
        __syncthreads();
        if (threadIdx.x == 0) s_running += chunk_tot;
        __syncthreads();
    }
}

// ---------------- layer-1 scatter (kept edges), 8 thr/edge --------------------
__global__ void scatter1_k(const int* __restrict__ src, const int* __restrict__ dst,
                           const float* __restrict__ node_repr, const float* __restrict__ vscore,
                           float* __restrict__ score_out) {
    unsigned gid = blockIdx.x * (unsigned)blockDim.x + threadIdx.x;
    int i = (int)(gid >> 3), q = (int)(gid & 7);
    if (i >= dKcount) return;
    int e = dKlist[i];
    int s = src[e], d = dst[e];
    float w = dEx[e];
    float4 v = *reinterpret_cast<const float4*>(&node_repr[s * 32 + q * 4]);
    red4(&dAgg[d * 32 + q * 4], w * v.x, w * v.y, w * v.z, w * v.w);
    if (q == 0) atomicAdd(&score_out[d], w * vscore[s]);
}

// ---------------- layer-0 scatter (all edges), fused normalize ----------------
__global__ void scatter0_k(const int* __restrict__ src, const int* __restrict__ dst, int E) {
    unsigned gid = blockIdx.x * (unsigned)blockDim.x + threadIdx.x;
    int e = (int)(gid >> 3), q = (int)(gid & 7);
    if (e >= E) return;
    int s = src[e], d = dst[e];
    float w = __fdividef(dEx[e], dNodeSum[s]);
    float4 v = *reinterpret_cast<const float4*>(&dRepr[s * 32 + q * 4]);
    red4(&dAgg[d * 32 + q * 4], w * v.x, w * v.y, w * v.z, w * v.w);
}

// ---------------- final bypass: LeakyReLU(Wlin r2 + blin) ---------------------
__global__ void __launch_bounds__(128, 6) final3_k(const float* __restrict__ Wlin,
                                                   const float* __restrict__ blin,
                                                   float* __restrict__ out_repr, int N) {
    __shared__ __align__(16) float sW[1024];
    __shared__ float sR[128 * 33];
    __shared__ float sB[32];
    int t = threadIdx.x;
    for (int i = t; i < 1024; i += 128) sW[i] = Wlin[i];
    if (t < 32) sB[t] = blin[t];
    int base = blockIdx.x * 128;
    for (int i = t; i < 128 * 32; i += 128) {
        int n = base + (i >> 5);
        float v = 0.f;
        if (n < N) {
            int g = n * 32 + (i & 31);
            v = fmaf(0.8f, dAgg[g], 0.2f * dRepr[g]);
        }
        sR[(i >> 5) * 33 + (i & 31)] = v;
    }
    __syncthreads();
    float re[32];
    #pragma unroll
    for (int k = 0; k < 32; k++) re[k] = sR[t * 33 + k];
    const float4* Wv = reinterpret_cast<const float4*>(sW);
    bool live = (base + t) < N;
    #pragma unroll 1
    for (int h = 0; h < 2; h++) {
        float acc[16];
        #pragma unroll
        for (int o = 0; o < 16; o++) {
            int row = h * 16 + o;
            float a = sB[row];
            #pragma unroll
            for (int k4 = 0; k4 < 8; k4++) {
                float4 m = Wv[row * 8 + k4];
                a = fmaf(m.x, re[4 * k4 + 0], a);
                a = fmaf(m.y, re[4 * k4 + 1], a);
                a = fmaf(m.z, re[4 * k4 + 2], a);
                a = fmaf(m.w, re[4 * k4 + 3], a);
            }
            acc[o] = (a >= 0.f) ? a : 0.01f * a;
        }
        __syncthreads();
        if (live) {
            #pragma unroll
            for (int o = 0; o < 16; o++) sR[t * 17 + o] = acc[o];
        }
        __syncthreads();
        for (int i = t; i < 128 * 16; i += 128) {
            int n = base + (i >> 4);
            if (n < N) out_repr[n * 32 + h * 16 + (i & 15)] = sR[(i >> 4) * 17 + (i & 15)];
        }
    }
}

// ---------------- launcher ----------------------------------------------------
extern "C" void kernel_launch(void* const* d_in, const int* in_sizes, int n_in,
                              void* d_out, int out_size) {
    const float* vscore    = (const float*)d_in[0];
    const float* node_repr = (const float*)d_in[1];
    const int*   eg0       = (const int*)d_in[2];
    const int*   src0      = (const int*)d_in[3];
    const int*   dst0      = (const int*)d_in[4];
    const float* rel0      = (const float*)d_in[5];
    const int*   eg1       = (const int*)d_in[6];
    const int*   src1      = (const int*)d_in[7];
    const int*   dst1      = (const int*)d_in[8];
    const float* rel1      = (const float*)d_in[9];
    const float* qemb      = (const float*)d_in[10];
    const float* remb      = (const float*)d_in[11];
    const float* Wq        = (const float*)d_in[12];
    const float* Wk        = (const float*)d_in[13];
    const float* Wlin      = (const float*)d_in[14];
    const float* blin      = (const float*)d_in[15];
    const int*   maxep     = (n_in > 16) ? (const int*)d_in[16] : nullptr;

    int N  = in_sizes[0];
    int E0 = in_sizes[2];
    int E1 = in_sizes[6];
    int Q  = in_sizes[10] / 32;

    float* out_score = (float*)d_out;
    float* out_repr  = (float*)d_out + N;

    int nbn  = (N + 127) / 128;             // 128-thread node blocks
    int nq1  = (E1 + 511) / 512;
    int nq0  = (E0 + 511) / 512;
    int ebw0 = (E0 + 7) / 8;
    int ebw1 = (E1 + 7) / 8;
    int ebt0 = (E0 + 255) / 256;
    int ebt1 = (E1 + 255) / 256;
    int ebs0 = (E0 * 8 + 255) / 256;
    int ebs1 = (E1 * 8 + 255) / 256;
    int nrst = (N * 32 + 127) / 128;

    // ---- prep: M, per-query vectors, group offsets, resets ----
    prep_k<<<129 + Q + nrst, 128>>>(Wq, Wk, qemb, remb, eg1, out_score, N, E1, Q);

    // ---- quad terms for BOTH layers (only needs dM + rel) ----
    quad_k<<<nq1 + nq0, 256>>>(rel1, rel0, E1, E0, nq1);

    // ---- layer 1 (pruned) ----
    node_pre3_k<<<nbn, 128>>>(node_repr, 0, N);
    edge_lin_k<<<ebw1, 256>>>(src1, dst1, eg1, rel1, node_repr, 0, 1, E1);
    edge_exp_k<<<ebt1, 256>>>(src1, 1, E1);
    ts_k<<<ebt1, 256>>>(src1, vscore, E1);
    topk_k<<<Q, 256>>>(maxep);
    scatter1_k<<<ebs1, 256>>>(src1, dst1, node_repr, vscore, out_score);

    // ---- layer 0 (no pruning); node_pre fuses repr update + resets ----
    node_pre3_k<<<nbn, 128>>>(node_repr, 1, N);
    edge_lin_k<<<ebw0, 256>>>(src0, dst0, eg0, rel0, nullptr, 1, 0, E0);
    edge_exp_k<<<ebt0, 256>>>(src0, 0, E0);
    scatter0_k<<<ebs0, 256>>>(src0, dst0, E0);

    // ---- bypass_forward ----
    final3_k<<<nbn, 128>>>(Wlin, blin, out_repr, N);
}

// round 4
// speedup vs baseline: 3.1066x; 1.2835x over previous
#include <cuda_runtime.h>

// ---------------- problem-size capacities (fixed by dataset) ----------------
static const int NMAX  = 100000;
static const int EMAX  = 500000;
static const int QMAXC = 128;

// ---------------- device scratch (static; no allocation) --------------------
__device__ float    dM[128 * 128];          // M = Wq^T @ Wk
__device__ float    dGx[QMAXC * 32];
__device__ float    dGy[QMAXC * 32];
__device__ float    dGrel[QMAXC * 32];
__device__ float    dCq[QMAXC];
__device__ float    dZ[NMAX * 32];
__device__ float    dP[NMAX * 32];
__device__ float    dT[NMAX * 32];
__device__ float    dRepr[NMAX * 32];
__device__ float    dAgg[NMAX * 32];
__device__ float    dLogits1[EMAX];         // layer-1: quad term, then logit
__device__ float    dLogits0[EMAX];         // layer-0: quad term, then logit
__device__ float    dEx[EMAX];
__device__ unsigned dTsEnc[EMAX];
__device__ unsigned dNodeMax[NMAX];
__device__ float    dNodeSum[NMAX];
__device__ int      dOff[QMAXC + 1];
__device__ int      dKlist[EMAX];
__device__ int      dKcount;

// ---------------- helpers ----------------------------------------------------
__device__ __forceinline__ unsigned encf(float f) {
    unsigned u = __float_as_uint(f);
    return (u & 0x80000000u) ? ~u : (u | 0x80000000u);
}
__device__ __forceinline__ float decf(unsigned e) {
    unsigned u = (e & 0x80000000u) ? (e & 0x7FFFFFFFu) : ~e;
    return __uint_as_float(u);
}
__device__ __forceinline__ unsigned long long packf2(float lo, float hi) {
    unsigned long long r;
    asm("mov.b64 %0, {%1, %2};" : "=l"(r) : "f"(lo), "f"(hi));
    return r;
}
__device__ __forceinline__ void unpackf2(unsigned long long v, float& lo, float& hi) {
    asm("mov.b64 {%0, %1}, %2;" : "=f"(lo), "=f"(hi) : "l"(v));
}
__device__ __forceinline__ unsigned long long fmaf2(unsigned long long a, unsigned long long b,
                                                    unsigned long long c) {
    unsigned long long d;
    asm("fma.rn.f32x2 %0, %1, %2, %3;" : "=l"(d) : "l"(a), "l"(b), "l"(c));
    return d;
}
__device__ __forceinline__ void red4(float* p, float a, float b, float c, float d) {
    asm volatile("red.global.v4.f32.add [%0], {%1, %2, %3, %4};"
                 :: "l"(p), "f"(a), "f"(b), "f"(c), "f"(d) : "memory");
}

// ---------------- prep: computeM + query_pre + group_off + resets -------------
__global__ void __launch_bounds__(128) prep_k(const float* __restrict__ Wq,
                                              const float* __restrict__ Wk,
                                              const float* __restrict__ qemb,
                                              const float* __restrict__ remb,
                                              const int* __restrict__ eg1,
                                              float* __restrict__ score_out,
                                              int N, int E1, int Q) {
    int b = blockIdx.x, t = threadIdx.x;
    if (b < 128) {
        int i = b, j = t;
        float acc = 0.f;
        #pragma unroll 8
        for (int o = 0; o < 128; o++)
            acc = fmaf(__ldg(&Wq[o * 128 + i]), __ldg(&Wk[o * 128 + j]), acc);
        dM[i * 128 + j] = acc;
        return;
    }
    if (b < 128 + Q) {
        if (t >= 32) return;
        int q = b - 128, d = t;
        __shared__ float qv[32], rv[32];
        qv[d] = qemb[q * 32 + d];
        rv[d] = remb[q * 32 + d];
        __syncwarp();
        // u[o] = Wk[o][64:96]·qv + Wk[o][96:128]·rv ; v[o] = same with Wq
        // gx = Wq[:, d]·u ; gy = Wk[:, d]·v ; grel = Wq[:,32+d]·u + Wk[:,32+d]·v ; c = u·v
        __shared__ float su[128], sv[128];
        for (int o = d; o < 128; o += 32) {
            float uu = 0.f, vv = 0.f;
            #pragma unroll
            for (int c = 0; c < 32; c++) {
                uu = fmaf(__ldg(&Wk[o * 128 + 64 + c]), qv[c], uu);
                uu = fmaf(__ldg(&Wk[o * 128 + 96 + c]), rv[c], uu);
                vv = fmaf(__ldg(&Wq[o * 128 + 64 + c]), qv[c], vv);
                vv = fmaf(__ldg(&Wq[o * 128 + 96 + c]), rv[c], vv);
            }
            su[o] = uu; sv[o] = vv;
        }
        __syncwarp();
        float gx = 0.f, gy = 0.f, gr = 0.f, cq = 0.f;
        for (int o = 0; o < 128; o++) {
            float uo = su[o], vo = sv[o];
            gx = fmaf(__ldg(&Wq[o * 128 + d]), uo, gx);
            gy = fmaf(__ldg(&Wk[o * 128 + d]), vo, gy);
            gr = fmaf(__ldg(&Wq[o * 128 + 32 + d]), uo, gr);
            gr = fmaf(__ldg(&Wk[o * 128 + 32 + d]), vo, gr);
            if (d == 0) cq = fmaf(uo, vo, cq);
        }
        dGx[q * 32 + d] = gx;
        dGy[q * 32 + d] = gy;
        dGrel[q * 32 + d] = gr;
        if (d == 0) dCq[q] = cq;
        return;
    }
    if (b == 128 + Q) {
        for (int g = t; g <= Q; g += 128) {
            int lo = 0, hi = E1;
            while (lo < hi) {
                int mid = (lo + hi) >> 1;
                if (eg1[mid] < g) lo = mid + 1; else hi = mid;
            }
            dOff[g] = lo;
        }
        return;
    }
    int i = (b - (129 + Q)) * 128 + t;
    if (i < N * 32) dAgg[i] = 0.f;
    if (i < N) {
        dNodeMax[i] = 0u;
        dNodeSum[i] = 0.f;
        score_out[i] = 0.f;
    }
    if (i == 0) dKcount = 0;
}

// ---------------- node precompute: z/p/t (+ optional fused repr update) -------
__global__ void __launch_bounds__(128, 6) node_pre3_k(const float* __restrict__ repr_ext,
                                                      int mode, int N) {
    __shared__ __align__(16) float sW[96 * 32];
    __shared__ float sR[128 * 33];
    int t = threadIdx.x;
    for (int i = t; i < 96 * 32; i += 128) {
        int o = i >> 5, k = i & 31;
        float v;
        if (o < 32)      v = dM[o * 128 + k];
        else if (o < 64) v = dM[k * 128 + 32 + (o - 32)];
        else             v = dM[(32 + (o - 64)) * 128 + k];
        sW[i] = v;
    }
    int base = blockIdx.x * 128;
    if (mode == 0) {
        for (int i = t; i < 128 * 32; i += 128) {
            int n = base + (i >> 5);
            sR[(i >> 5) * 33 + (i & 31)] = (n < N) ? repr_ext[n * 32 + (i & 31)] : 0.f;
        }
    } else {
        for (int i = t; i < 128 * 32; i += 128) {
            int n = base + (i >> 5);
            float v = 0.f;
            if (n < N) {
                int g = n * 32 + (i & 31);
                v = fmaf(0.8f, dAgg[g], 0.2f * repr_ext[g]);
                dRepr[g] = v;
                dAgg[g] = 0.f;
            }
            sR[(i >> 5) * 33 + (i & 31)] = v;
        }
        int n = base + t;
        if (n < N) { dNodeMax[n] = 0u; dNodeSum[n] = 0.f; }
    }
    __syncthreads();
    float re[32];
    #pragma unroll
    for (int k = 0; k < 32; k++) re[k] = sR[t * 33 + k];

    const float4* Wv = reinterpret_cast<const float4*>(sW);
    bool live = (base + t) < N;
    #pragma unroll 1
    for (int c = 0; c < 3; c++) {
        float* out = (c == 0) ? dZ : (c == 1) ? dP : dT;
        #pragma unroll 1
        for (int h = 0; h < 2; h++) {
            float acc[16];
            #pragma unroll
            for (int o = 0; o < 16; o++) {
                int row = c * 32 + h * 16 + o;
                float a = 0.f;
                #pragma unroll
                for (int k4 = 0; k4 < 8; k4++) {
                    float4 m = Wv[row * 8 + k4];
                    a = fmaf(m.x, re[4 * k4 + 0], a);
                    a = fmaf(m.y, re[4 * k4 + 1], a);
                    a = fmaf(m.z, re[4 * k4 + 2], a);
                    a = fmaf(m.w, re[4 * k4 + 3], a);
                }
                acc[o] = a;
            }
            __syncthreads();
            if (live) {
                #pragma unroll
                for (int o = 0; o < 16; o++) sR[t * 17 + o] = acc[o];
            }
            __syncthreads();
            for (int i = t; i < 128 * 16; i += 128) {
                int n = base + (i >> 4);
                if (n < N) out[n * 32 + h * 16 + (i & 15)] = sR[(i >> 4) * 17 + (i & 15)];
            }
        }
    }
}

// ---------------- quadratic term, both layers, triangular form ----------------
__global__ void __launch_bounds__(256) quad_k(const float* __restrict__ rel1,
                                              const float* __restrict__ rel0,
                                              int E1, int E0, int nq1) {
    __shared__ __align__(16) unsigned long long sTri[528];
    __shared__ float sRe[256 * 33];
    int t = threadIdx.x;
    for (int i = t; i < 528; i += 256) {
        int j = 0, off = 0;
        while (off + (32 - j) <= i) { off += 32 - j; j++; }
        int k = j + (i - off);
        float v = (k == j) ? dM[(32 + j) * 128 + 32 + j]
                           : dM[(32 + j) * 128 + 32 + k] + dM[(32 + k) * 128 + 32 + j];
        sTri[i] = packf2(v, v);
    }
    bool l1 = blockIdx.x < nq1;
    const float* rel = l1 ? rel1 : rel0;
    float* out = l1 ? dLogits1 : dLogits0;
    int E = l1 ? E1 : E0;
    int base = (l1 ? blockIdx.x : blockIdx.x - nq1) * 512;

    for (int i = t; i < 256 * 32; i += 256) {
        int e = base + (i >> 5);
        sRe[(i >> 5) * 33 + (i & 31)] = (e < E) ? rel[(size_t)e * 32 + (i & 31)] : 0.f;
    }
    __syncthreads();
    float reA[32];
    #pragma unroll
    for (int k = 0; k < 32; k++) reA[k] = sRe[t * 33 + k];
    __syncthreads();
    for (int i = t; i < 256 * 32; i += 256) {
        int e = base + 256 + (i >> 5);
        sRe[(i >> 5) * 33 + (i & 31)] = (e < E) ? rel[(size_t)e * 32 + (i & 31)] : 0.f;
    }
    __syncthreads();
    unsigned long long re2[32];
    #pragma unroll
    for (int k = 0; k < 32; k++) re2[k] = packf2(reA[k], sRe[t * 33 + k]);

    const unsigned long long z2 = packf2(0.f, 0.f);
    unsigned long long w2 = z2;
    #pragma unroll
    for (int j = 0; j < 32; j++) {
        const int off = 32 * j - (j * (j - 1)) / 2;
        unsigned long long v2 = fmaf2(sTri[off], re2[j], z2);
        #pragma unroll
        for (int k = j + 1; k < 32; k++)
            v2 = fmaf2(sTri[off + (k - j)], re2[k], v2);
        w2 = fmaf2(re2[j], v2, w2);
    }
    float wA, wB;
    unpackf2(w2, wA, wB);
    int eA = base + t, eB = base + 256 + t;
    if (eA < E) out[eA] = wA;
    if (eB < E) out[eB] = wB;
}

// ---------------- linear logit terms: 4 edges per warp, 8 lanes each ----------
__global__ void __launch_bounds__(256) edge_lin4_k(const int* __restrict__ src,
                                                   const int* __restrict__ dst,
                                                   const int* __restrict__ eg,
                                                   const float* __restrict__ rel,
                                                   const float* repr_ext, int use_internal,
                                                   int layer1, int E) {
    const float* repr = use_internal ? dRepr : repr_ext;
    float* lgt = layer1 ? dLogits1 : dLogits0;
    unsigned gid = blockIdx.x * (unsigned)blockDim.x + threadIdx.x;
    int e = (int)(gid >> 3);          // 8 lanes per edge
    int q = (int)(gid & 7);
    bool valid = e < E;
    int ee = valid ? e : 0;
    int s = __ldg(&src[ee]), d = __ldg(&dst[ee]), g = __ldg(&eg[ee]);

    float4 x  = *reinterpret_cast<const float4*>(&repr[s * 32 + q * 4]);
    float4 y  = *reinterpret_cast<const float4*>(&repr[d * 32 + q * 4]);
    float4 zz = *reinterpret_cast<const float4*>(&dZ[d * 32 + q * 4]);
    float4 pp = *reinterpret_cast<const float4*>(&dP[s * 32 + q * 4]);
    float4 tt = *reinterpret_cast<const float4*>(&dT[d * 32 + q * 4]);
    float4 re = *reinterpret_cast<const float4*>(&rel[(size_t)ee * 32 + q * 4]);
    float4 gx = *reinterpret_cast<const float4*>(&dGx[g * 32 + q * 4]);
    float4 gy = *reinterpret_cast<const float4*>(&dGy[g * 32 + q * 4]);
    float4 gr = *reinterpret_cast<const float4*>(&dGrel[g * 32 + q * 4]);

    float part = x.x * (zz.x + gx.x) + x.y * (zz.y + gx.y)
               + x.z * (zz.z + gx.z) + x.w * (zz.w + gx.w);
    part = fmaf(y.x, gy.x, part); part = fmaf(y.y, gy.y, part);
    part = fmaf(y.z, gy.z, part); part = fmaf(y.w, gy.w, part);
    part = fmaf(re.x, pp.x + tt.x + gr.x, part);
    part = fmaf(re.y, pp.y + tt.y + gr.y, part);
    part = fmaf(re.z, pp.z + tt.z + gr.z, part);
    part = fmaf(re.w, pp.w + tt.w + gr.w, part);

    part += __shfl_xor_sync(0xffffffffu, part, 1);
    part += __shfl_xor_sync(0xffffffffu, part, 2);
    part += __shfl_xor_sync(0xffffffffu, part, 4);

    if (valid && q == 0) {
        float logit = part + lgt[e] + dCq[g];
        lgt[e] = logit;
        atomicMax(&dNodeMax[s], encf(logit));
    }
}

// ---------------- exp(logit - max) + per-src sum -------------------------------
__global__ void edge_exp_k(const int* __restrict__ src, int layer1, int E) {
    int e = blockIdx.x * blockDim.x + threadIdx.x;
    if (e >= E) return;
    int s = src[e];
    float m = decf(dNodeMax[s]);
    float lg = layer1 ? dLogits1[e] : dLogits0[e];
    float ex = __expf(lg - m);
    dEx[e] = ex;
    atomicAdd(&dNodeSum[s], ex);
}

// ---------------- normalize + encoded target score (layer 1) ------------------
__global__ void ts_k(const int* __restrict__ src, const float* __restrict__ vscore, int E) {
    int e = blockIdx.x * blockDim.x + threadIdx.x;
    if (e >= E) return;
    int s = src[e];
    float w = __fdividef(dEx[e], dNodeSum[s]);
    dEx[e] = w;
    dTsEnc[e] = __float_as_uint(w * vscore[s]);
}

// ---------------- per-group top-k (stable: value desc, index asc) -------------
__global__ void topk_k(const int* maxe) {
    int g = blockIdx.x;
    int lo = dOff[g], hi = dOff[g + 1];
    int len = hi - lo;
    if (len <= 0) return;
    int K = maxe ? maxe[0] : 500;
    if (K > len) K = len;

    __shared__ int hist[256];
    __shared__ int s_selbin, s_rem;
    unsigned prefix = 0u;
    int remaining = K;
    for (int shift = 24; shift >= 0; shift -= 8) {
        unsigned mask_hi = (shift == 24) ? 0u : (0xFFFFFFFFu << (shift + 8));
        for (int i = threadIdx.x; i < 256; i += blockDim.x) hist[i] = 0;
        __syncthreads();
        for (int i = lo + threadIdx.x; i < hi; i += blockDim.x) {
            unsigned v = dTsEnc[i];
            if ((v & mask_hi) == prefix) atomicAdd(&hist[(v >> shift) & 255], 1);
        }
        __syncthreads();
        if (threadIdx.x == 0) {
            int cum = 0, b = 255;
            for (; b > 0; b--) { cum += hist[b]; if (cum >= remaining) break; }
            if (cum < remaining) cum += hist[0];
            s_selbin = b;
            s_rem = remaining - (cum - hist[b]);
        }
        __syncthreads();
        prefix |= ((unsigned)s_selbin) << shift;
        remaining = s_rem;
        __syncthreads();
    }
    unsigned T = prefix;
    int quota_eq = remaining;

    __shared__ int warp_cnt[8];
    __shared__ int s_running;
    if (threadIdx.x == 0) s_running = 0;
    __syncthreads();
    for (int base = lo; base < hi; base += blockDim.x) {
        int i = base + (int)threadIdx.x;
        bool valid = i < hi;
        unsigned v = valid ? dTsEnc[i] : 0u;
        bool gt = valid && (v > T);
        bool eq = valid && (v == T);
        unsigned bal = __ballot_sync(0xffffffffu, eq);
        int lane = threadIdx.x & 31, wrp = threadIdx.x >> 5;
        int myrank = __popc(bal & ((1u << lane) - 1u));
        if (lane == 0) warp_cnt[wrp] = __popc(bal);
        __syncthreads();
        int woff = 0, chunk_tot = 0;
        #pragma unroll
        for (int ww = 0; ww < 8; ww++) {
            int c = warp_cnt[ww];
            if (ww < wrp) woff += c;
            chunk_tot += c;
        }
        int rank = s_running + woff + myrank;
        bool keep = gt || (eq && rank < quota_eq);
        if (keep) {
            int pos = atomicAdd(&dKcount, 1);
            dKlist[pos] = i;
        }
        __syncthreads();
        if (threadIdx.x == 0) s_running += chunk_tot;
        __syncthreads();
    }
}

// ---------------- layer-1 scatter (kept edges), 8 thr/edge --------------------
__global__ void scatter1_k(const int* __restrict__ src, const int* __restrict__ dst,
                           const float* __restrict__ node_repr, const float* __restrict__ vscore,
                           float* __restrict__ score_out) {
    unsigned gid = blockIdx.x * (unsigned)blockDim.x + threadIdx.x;
    int i = (int)(gid >> 3), q = (int)(gid & 7);
    if (i >= dKcount) return;
    int e = dKlist[i];
    int s = src[e], d = dst[e];
    float w = dEx[e];
    float4 v = *reinterpret_cast<const float4*>(&node_repr[s * 32 + q * 4]);
    red4(&dAgg[d * 32 + q * 4], w * v.x, w * v.y, w * v.z, w * v.w);
    if (q == 0) atomicAdd(&score_out[d], w * vscore[s]);
}

// ---------------- layer-0 scatter (all edges), fused normalize ----------------
__global__ void scatter0_k(const int* __restrict__ src, const int* __restrict__ dst, int E) {
    unsigned gid = blockIdx.x * (unsigned)blockDim.x + threadIdx.x;
    int e = (int)(gid >> 3), q = (int)(gid & 7);
    if (e >= E) return;
    int s = src[e], d = dst[e];
    float w = __fdividef(dEx[e], dNodeSum[s]);
    float4 v = *reinterpret_cast<const float4*>(&dRepr[s * 32 + q * 4]);
    red4(&dAgg[d * 32 + q * 4], w * v.x, w * v.y, w * v.z, w * v.w);
}

// ---------------- final bypass: LeakyReLU(Wlin r2 + blin) ---------------------
__global__ void __launch_bounds__(128, 6) final3_k(const float* __restrict__ Wlin,
                                                   const float* __restrict__ blin,
                                                   float* __restrict__ out_repr, int N) {
    __shared__ __align__(16) float sW[1024];
    __shared__ float sR[128 * 33];
    __shared__ float sB[32];
    int t = threadIdx.x;
    for (int i = t; i < 1024; i += 128) sW[i] = Wlin[i];
    if (t < 32) sB[t] = blin[t];
    int base = blockIdx.x * 128;
    for (int i = t; i < 128 * 32; i += 128) {
        int n = base + (i >> 5);
        float v = 0.f;
        if (n < N) {
            int g = n * 32 + (i & 31);
            v = fmaf(0.8f, dAgg[g], 0.2f * dRepr[g]);
        }
        sR[(i >> 5) * 33 + (i & 31)] = v;
    }
    __syncthreads();
    float re[32];
    #pragma unroll
    for (int k = 0; k < 32; k++) re[k] = sR[t * 33 + k];
    const float4* Wv = reinterpret_cast<const float4*>(sW);
    bool live = (base + t) < N;
    #pragma unroll 1
    for (int h = 0; h < 2; h++) {
        float acc[16];
        #pragma unroll
        for (int o = 0; o < 16; o++) {
            int row = h * 16 + o;
            float a = sB[row];
            #pragma unroll
            for (int k4 = 0; k4 < 8; k4++) {
                float4 m = Wv[row * 8 + k4];
                a = fmaf(m.x, re[4 * k4 + 0], a);
                a = fmaf(m.y, re[4 * k4 + 1], a);
                a = fmaf(m.z, re[4 * k4 + 2], a);
                a = fmaf(m.w, re[4 * k4 + 3], a);
            }
            acc[o] = (a >= 0.f) ? a : 0.01f * a;
        }
        __syncthreads();
        if (live) {
            #pragma unroll
            for (int o = 0; o < 16; o++) sR[t * 17 + o] = acc[o];
        }
        __syncthreads();
        for (int i = t; i < 128 * 16; i += 128) {
            int n = base + (i >> 4);
            if (n < N) out_repr[n * 32 + h * 16 + (i & 15)] = sR[(i >> 4) * 17 + (i & 15)];
        }
    }
}

// ---------------- launcher ----------------------------------------------------
extern "C" void kernel_launch(void* const* d_in, const int* in_sizes, int n_in,
                              void* d_out, int out_size) {
    const float* vscore    = (const float*)d_in[0];
    const float* node_repr = (const float*)d_in[1];
    const int*   eg0       = (const int*)d_in[2];
    const int*   src0      = (const int*)d_in[3];
    const int*   dst0      = (const int*)d_in[4];
    const float* rel0      = (const float*)d_in[5];
    const int*   eg1       = (const int*)d_in[6];
    const int*   src1      = (const int*)d_in[7];
    const int*   dst1      = (const int*)d_in[8];
    const float* rel1      = (const float*)d_in[9];
    const float* qemb      = (const float*)d_in[10];
    const float* remb      = (const float*)d_in[11];
    const float* Wq        = (const float*)d_in[12];
    const float* Wk        = (const float*)d_in[13];
    const float* Wlin      = (const float*)d_in[14];
    const float* blin      = (const float*)d_in[15];
    const int*   maxep     = (n_in > 16) ? (const int*)d_in[16] : nullptr;

    int N  = in_sizes[0];
    int E0 = in_sizes[2];
    int E1 = in_sizes[6];
    int Q  = in_sizes[10] / 32;

    float* out_score = (float*)d_out;
    float* out_repr  = (float*)d_out + N;

    int nbn  = (N + 127) / 128;
    int nq1  = (E1 + 511) / 512;
    int nq0  = (E0 + 511) / 512;
    int ebl0 = (E0 * 8 + 255) / 256;        // 8 lanes/edge
    int ebl1 = (E1 * 8 + 255) / 256;
    int ebt0 = (E0 + 255) / 256;
    int ebt1 = (E1 + 255) / 256;
    int nrst = (N * 32 + 127) / 128;

    // ---- prep: M, per-query vectors, group offsets, resets ----
    prep_k<<<129 + Q + nrst, 128>>>(Wq, Wk, qemb, remb, eg1, out_score, N, E1, Q);

    // ---- quad terms for BOTH layers ----
    quad_k<<<nq1 + nq0, 256>>>(rel1, rel0, E1, E0, nq1);

    // ---- layer 1 (pruned) ----
    node_pre3_k<<<nbn, 128>>>(node_repr, 0, N);
    edge_lin4_k<<<ebl1, 256>>>(src1, dst1, eg1, rel1, node_repr, 0, 1, E1);
    edge_exp_k<<<ebt1, 256>>>(src1, 1, E1);
    ts_k<<<ebt1, 256>>>(src1, vscore, E1);
    topk_k<<<Q, 256>>>(maxep);
    scatter1_k<<<ebl1, 256>>>(src1, dst1, node_repr, vscore, out_score);

    // ---- layer 0 (no pruning); node_pre fuses repr update + resets ----
    node_pre3_k<<<nbn, 128>>>(node_repr, 1, N);
    edge_lin4_k<<<ebl0, 256>>>(src0, dst0, eg0, rel0, nullptr, 1, 0, E0);
    edge_exp_k<<<ebt0, 256>>>(src0, 0, E0);
    scatter0_k<<<ebl0, 256>>>(src0, dst0, E0);

    // ---- bypass_forward ----
    final3_k<<<nbn, 128>>>(Wlin, blin, out_repr, N);
}